// round 2
// baseline (speedup 1.0000x reference)
#include <cuda_runtime.h>
#include <math.h>

#define N_NODES 30000
#define N_EDGES 480000
#define HID 256
#define HEADS 8
#define OUTC 32
#define LAYERS 6
#define NODE_IN 13
#define EDGE_IN 10
#define BN_EPS 1e-5f
#define HALF_HID (HID/2)

// ---------------- static scratch (no runtime allocation allowed) ----------------
__device__ __align__(256) float g_h[2][N_NODES*HID];
__device__ __align__(256) float g_xl[N_NODES*HID];
__device__ __align__(256) float g_xr[N_NODES*HID];
__device__ __align__(256) float g_t[N_NODES*HALF_HID];
__device__ __align__(256) float g_A[2][EDGE_IN*HID];
__device__ __align__(256) float g_bv[2][HID];
__device__ __align__(256) float g_M[LAYERS][EDGE_IN*HID];
__device__ __align__(256) float g_cvec[LAYERS][HID];
__device__ __align__(256) int   g_row_ptr[N_NODES+1];
__device__ __align__(256) int   g_cursor[N_NODES];
__device__ __align__(256) int   g_sorted[N_EDGES];

// ---------------- CSR build ----------------
__global__ void zero_int_k(int* p, int n){
    for (int i = blockIdx.x*blockDim.x + threadIdx.x; i < n; i += gridDim.x*blockDim.x) p[i] = 0;
}

__global__ void hist_k(const int* __restrict__ dst, int* __restrict__ deg, int n){
    for (int i = blockIdx.x*blockDim.x + threadIdx.x; i < n; i += gridDim.x*blockDim.x)
        atomicAdd(&deg[dst[i]], 1);
}

// single-block scan: deg_cursor holds degrees on input; on output row_ptr gets
// inclusive offsets (row_ptr[0]=0) and deg_cursor gets exclusive offsets (write cursors)
__global__ void scan_k(int* __restrict__ deg_cursor, int* __restrict__ row_ptr, int n){
    __shared__ int wsum[32];
    __shared__ int s_carry;
    int t = threadIdx.x, lane = t & 31, wid = t >> 5;
    if (t == 0){ s_carry = 0; row_ptr[0] = 0; }
    __syncthreads();
    for (int base = 0; base < n; base += 1024){
        int idx = base + t;
        int v = (idx < n) ? deg_cursor[idx] : 0;
        int x = v;
        #pragma unroll
        for (int o = 1; o < 32; o <<= 1){ int y = __shfl_up_sync(0xffffffffu, x, o); if (lane >= o) x += y; }
        if (lane == 31) wsum[wid] = x;
        __syncthreads();
        if (wid == 0){
            int s = wsum[lane];
            #pragma unroll
            for (int o = 1; o < 32; o <<= 1){ int y = __shfl_up_sync(0xffffffffu, s, o); if (lane >= o) s += y; }
            wsum[lane] = s;
        }
        __syncthreads();
        int c = s_carry;
        int incl = x + (wid ? wsum[wid-1] : 0) + c;
        if (idx < n){ row_ptr[idx+1] = incl; deg_cursor[idx] = incl - v; }
        __syncthreads();
        if (t == 0) s_carry = c + wsum[31];
        __syncthreads();
    }
}

__global__ void scatter_k(const int* __restrict__ dst, int* __restrict__ cursor,
                          int* __restrict__ sorted, int n){
    for (int i = blockIdx.x*blockDim.x + threadIdx.x; i < n; i += gridDim.x*blockDim.x){
        int p = atomicAdd(&cursor[dst[i]], 1);
        sorted[p] = i;
    }
}

// ---------------- initial node embedding: h = x @ node_W + node_b ----------------
#define NODES_PER_BLK 16
__global__ void init_h_k(const float* __restrict__ x, const float* __restrict__ W,
                         const float* __restrict__ b, float* __restrict__ h, int n){
    __shared__ float Ws[NODE_IN*HID];
    int t = threadIdx.x;
    #pragma unroll
    for (int j = 0; j < NODE_IN; j++) Ws[j*HID + t] = W[j*HID + t];
    __syncthreads();
    float bb = b[t];
    int n0 = blockIdx.x * NODES_PER_BLK;
    for (int nn = 0; nn < NODES_PER_BLK; nn++){
        int node = n0 + nn;
        if (node >= n) break;
        float s = bb;
        #pragma unroll
        for (int k = 0; k < NODE_IN; k++) s += __ldg(&x[node*NODE_IN + k]) * Ws[k*HID + t];
        h[node*HID + t] = s;
    }
}

// ---------------- edge-feature affine chain ----------------
__global__ void initA_k(const float* __restrict__ edge_W, const float* __restrict__ edge_b,
                        float* __restrict__ A, float* __restrict__ bv){
    int i = blockIdx.x*blockDim.x + threadIdx.x;
    if (i < EDGE_IN*HID) A[i] = edge_W[i];
    if (i < HID) bv[i] = edge_b[i];
}

// M = A @ We_i  (10x256), cvec = bvec @ We_i
__global__ void chainM_k(const float* __restrict__ A, const float* __restrict__ bvec,
                         const float* __restrict__ We_i, float* __restrict__ Mo, float* __restrict__ cvo){
    int c = threadIdx.x; int k = blockIdx.x;
    float s = 0.f;
    if (k < EDGE_IN){
        for (int j = 0; j < HID; j++) s += A[k*HID + j] * We_i[j*HID + c];
        Mo[k*HID + c] = s;
    } else {
        for (int j = 0; j < HID; j++) s += bvec[j] * We_i[j*HID + c];
        cvo[c] = s;
    }
}

// A' = A @ Weu_i, b' = bvec @ Weu_i + beu_i
__global__ void chainU_k(const float* __restrict__ A, const float* __restrict__ bvec,
                         const float* __restrict__ Weu_i, const float* __restrict__ beu_i,
                         float* __restrict__ Ao, float* __restrict__ bo){
    int c = threadIdx.x; int k = blockIdx.x;
    float s = 0.f;
    if (k < EDGE_IN){
        for (int j = 0; j < HID; j++) s += A[k*HID + j] * Weu_i[j*HID + c];
        Ao[k*HID + c] = s;
    } else {
        for (int j = 0; j < HID; j++) s += bvec[j] * Weu_i[j*HID + c];
        bo[c] = s + beu_i[c];
    }
}

// ---------------- SGEMM: C[M,N] = A[M,K] @ B[K,N] + bias (+ optional leaky) ----------------
// BM=128, BN=128, BK=8, 256 threads, 8x8 outputs per thread, 2-stage smem pipeline
__global__ __launch_bounds__(256, 2)
void sgemm_k(const float* __restrict__ A, const float* __restrict__ B,
             const float* __restrict__ bias, float* __restrict__ C,
             int M, int N, int K, float slope, int leaky)
{
    __shared__ __align__(16) float As[2][8][128];
    __shared__ __align__(16) float Bs[2][8][128];
    int tid = threadIdx.x;
    int row0 = blockIdx.y * 128, col0 = blockIdx.x * 128;
    int tr = tid >> 4, tc = tid & 15;

    float acc[8][8];
    #pragma unroll
    for (int i = 0; i < 8; i++)
        #pragma unroll
        for (int j = 0; j < 8; j++) acc[i][j] = 0.f;

    const int ar  = tid >> 1;          // A row within tile (0..127)
    const int akq = (tid & 1) * 4;     // A k-quad (0 or 4)
    const int bk  = tid >> 5;          // B k-row (0..7)
    const int bc  = (tid & 31) * 4;    // B col quad
    const int grow = row0 + ar;
    const float* Aptr = A + (size_t)grow*K + akq;
    const float* Bptr = B + (size_t)bk*N + col0 + bc;

    // prologue: load tile 0 into buffer 0
    {
        float4 av = make_float4(0.f,0.f,0.f,0.f);
        if (grow < M) av = *(const float4*)(Aptr);
        As[0][akq+0][ar] = av.x; As[0][akq+1][ar] = av.y;
        As[0][akq+2][ar] = av.z; As[0][akq+3][ar] = av.w;
        *(float4*)&Bs[0][bk][bc] = *(const float4*)(Bptr);
    }
    __syncthreads();

    int nk = K >> 3;
    for (int kt = 0; kt < nk; kt++){
        int buf = kt & 1;
        float4 av, bv4;
        bool has_next = (kt + 1 < nk);
        if (has_next){
            int k0 = (kt + 1) << 3;
            av = make_float4(0.f,0.f,0.f,0.f);
            if (grow < M) av = *(const float4*)(Aptr + k0);
            bv4 = *(const float4*)(Bptr + (size_t)k0*N);
        }
        #pragma unroll
        for (int kk = 0; kk < 8; kk++){
            float a[8], b[8];
            *(float4*)&a[0] = *(const float4*)&As[buf][kk][tr*8];
            *(float4*)&a[4] = *(const float4*)&As[buf][kk][tr*8+4];
            *(float4*)&b[0] = *(const float4*)&Bs[buf][kk][tc*8];
            *(float4*)&b[4] = *(const float4*)&Bs[buf][kk][tc*8+4];
            #pragma unroll
            for (int i = 0; i < 8; i++)
                #pragma unroll
                for (int j = 0; j < 8; j++) acc[i][j] += a[i]*b[j];
        }
        if (has_next){
            int nb = buf ^ 1;
            As[nb][akq+0][ar] = av.x; As[nb][akq+1][ar] = av.y;
            As[nb][akq+2][ar] = av.z; As[nb][akq+3][ar] = av.w;
            *(float4*)&Bs[nb][bk][bc] = bv4;
        }
        __syncthreads();
    }

    #pragma unroll
    for (int i = 0; i < 8; i++){
        int row = row0 + tr*8 + i;
        if (row >= M) continue;
        #pragma unroll
        for (int j = 0; j < 8; j++){
            int col = col0 + tc*8 + j;
            float v = acc[i][j] + bias[col];
            if (leaky) v = v >= 0.f ? v : slope*v;
            C[(size_t)row*N + col] = v;
        }
    }
}

// ---------------- fused GATv2 edge phase + BN + leaky + residual ----------------
// one block per destination node (256 threads), one warp per head (lane = channel in head)
__global__ __launch_bounds__(256)
void gat_k(const float* __restrict__ xl, const float* __restrict__ xr,
           const float* __restrict__ h_in, float* __restrict__ h_out,
           const int* __restrict__ src, const float* __restrict__ ea,
           const int* __restrict__ row_ptr, const int* __restrict__ sorted,
           const float* __restrict__ Mmat, const float* __restrict__ cvec,
           const float* __restrict__ att, const float* __restrict__ conv_b,
           const float* __restrict__ bn_g, const float* __restrict__ bn_b,
           const float* __restrict__ bn_rm, const float* __restrict__ bn_rv,
           int add_res)
{
    __shared__ float Msh[EDGE_IN*HID];
    int t = threadIdx.x;          // channel 0..255; warp = head
    #pragma unroll
    for (int j = 0; j < EDGE_IN; j++) Msh[j*HID + t] = Mmat[j*HID + t];
    int dst = blockIdx.x;
    float xrv  = xr[dst*HID + t];
    float attv = att[t];
    float base = xrv + cvec[t];
    int rs = row_ptr[dst], re = row_ptr[dst+1];
    float mmax = -INFINITY, den = 0.f, acc = 0.f;
    __syncthreads();
    for (int p = rs; p < re; p++){
        int e = sorted[p];
        int s = src[e];
        float xlv = __ldg(&xl[s*HID + t]);
        const float* eav = ea + (size_t)e*EDGE_IN;
        float v = base + xlv;
        #pragma unroll
        for (int j = 0; j < EDGE_IN; j++) v += __ldg(&eav[j]) * Msh[j*HID + t];
        v = v >= 0.f ? v : 0.2f*v;
        float lg = v * attv;
        #pragma unroll
        for (int o = 16; o > 0; o >>= 1) lg += __shfl_xor_sync(0xffffffffu, lg, o);
        if (lg <= mmax){
            float ee = expf(lg - mmax);
            den += ee; acc += ee * xlv;
        } else {
            float sc = expf(mmax - lg);   // 0 on first edge (mmax = -inf)
            den = den*sc + 1.f;
            acc = acc*sc + xlv;
            mmax = lg;
        }
    }
    float hn = acc / (den + 1e-16f) + conv_b[t];
    hn = (hn - bn_rm[t]) * rsqrtf(bn_rv[t] + BN_EPS) * bn_g[t] + bn_b[t];
    hn = hn >= 0.f ? hn : 0.01f*hn;
    if (add_res) hn += h_in[dst*HID + t];
    h_out[dst*HID + t] = hn;
}

// ---------------- output head: out[n] = leaky(h@W1+b1,.01) @ W2 + b2 (GEMM1 done by sgemm_k) ----------------
__global__ void out_k(const float* __restrict__ tbuf, const float* __restrict__ W2,
                      const float* __restrict__ b2, float* __restrict__ out, int n){
    int g = blockIdx.x*blockDim.x + threadIdx.x;
    int node = g >> 5, lane = g & 31;
    if (node >= n) return;
    float s = 0.f;
    #pragma unroll
    for (int j = lane; j < HALF_HID; j += 32) s += tbuf[node*HALF_HID + j] * __ldg(&W2[j]);
    #pragma unroll
    for (int o = 16; o > 0; o >>= 1) s += __shfl_xor_sync(0xffffffffu, s, o);
    if (lane == 0) out[node] = s + b2[0];
}

// ---------------- host ----------------
extern "C" void kernel_launch(void* const* d_in, const int* in_sizes, int n_in,
                              void* d_out, int out_size)
{
    const float* x      = (const float*)d_in[0];
    const int*   eidx   = (const int*)  d_in[1];
    const float* ea     = (const float*)d_in[2];
    const float* node_W = (const float*)d_in[3];
    const float* node_b = (const float*)d_in[4];
    const float* edge_W = (const float*)d_in[5];
    const float* edge_b = (const float*)d_in[6];
    const float* Wl     = (const float*)d_in[7];
    const float* bl     = (const float*)d_in[8];
    const float* Wr     = (const float*)d_in[9];
    const float* br     = (const float*)d_in[10];
    const float* We     = (const float*)d_in[11];
    const float* att    = (const float*)d_in[12];
    const float* conv_b = (const float*)d_in[13];
    const float* Weu    = (const float*)d_in[14];
    const float* beu    = (const float*)d_in[15];
    const float* bn_g   = (const float*)d_in[16];
    const float* bn_b   = (const float*)d_in[17];
    const float* bn_rm  = (const float*)d_in[18];
    const float* bn_rv  = (const float*)d_in[19];
    const float* oW1    = (const float*)d_in[20];
    const float* ob1    = (const float*)d_in[21];
    const float* oW2    = (const float*)d_in[22];
    const float* ob2    = (const float*)d_in[23];
    float* out = (float*)d_out;

    const int nN = in_sizes[0] / NODE_IN;   // 30000
    const int nE = in_sizes[1] / 2;         // 480000
    const int* srcp = eidx;
    const int* dstp = eidx + nE;

    void* p;
    cudaGetSymbolAddress(&p, g_h);      float* h0 = (float*)p; float* h1 = h0 + (size_t)N_NODES*HID;
    cudaGetSymbolAddress(&p, g_xl);     float* xl = (float*)p;
    cudaGetSymbolAddress(&p, g_xr);     float* xr = (float*)p;
    cudaGetSymbolAddress(&p, g_t);      float* tp = (float*)p;
    cudaGetSymbolAddress(&p, g_A);      float* A0 = (float*)p; float* A1 = A0 + EDGE_IN*HID;
    cudaGetSymbolAddress(&p, g_bv);     float* b0 = (float*)p; float* b1 = b0 + HID;
    cudaGetSymbolAddress(&p, g_M);      float* gM = (float*)p;
    cudaGetSymbolAddress(&p, g_cvec);   float* gcv = (float*)p;
    cudaGetSymbolAddress(&p, g_row_ptr);int* rp = (int*)p;
    cudaGetSymbolAddress(&p, g_cursor); int* cur = (int*)p;
    cudaGetSymbolAddress(&p, g_sorted); int* sorted = (int*)p;

    // CSR build (counting sort by destination)
    zero_int_k<<<128, 256>>>(cur, nN);
    hist_k<<<(nE + 255)/256, 256>>>(dstp, cur, nE);
    scan_k<<<1, 1024>>>(cur, rp, nN);
    scatter_k<<<(nE + 255)/256, 256>>>(dstp, cur, sorted, nE);

    // initial node embedding
    init_h_k<<<(nN + NODES_PER_BLK - 1)/NODES_PER_BLK, HID>>>(x, node_W, node_b, h0, nN);

    // edge-feature affine chain -> per-layer M (10x256) and cvec (256)
    initA_k<<<(EDGE_IN*HID + 255)/256, 256>>>(edge_W, edge_b, A0, b0);
    {
        float* Ai = A0; float* bi = b0; float* Ao = A1; float* bo = b1;
        for (int i = 0; i < LAYERS; i++){
            chainM_k<<<EDGE_IN + 1, HID>>>(Ai, bi, We + (size_t)i*HID*HID,
                                           gM + (size_t)i*EDGE_IN*HID, gcv + (size_t)i*HID);
            if (i < LAYERS - 1){
                chainU_k<<<EDGE_IN + 1, HID>>>(Ai, bi, Weu + (size_t)i*HID*HID, beu + (size_t)i*HID, Ao, bo);
                float* tA = Ai; Ai = Ao; Ao = tA;
                float* tb = bi; bi = bo; bo = tb;
            }
        }
    }

    // layer loop
    dim3 ggrid(HID/128, (nN + 127)/128);
    int cb = 0;
    for (int i = 0; i < LAYERS; i++){
        float* hin  = cb ? h1 : h0;
        float* hout = cb ? h0 : h1;
        sgemm_k<<<ggrid, 256>>>(hin, Wl + (size_t)i*HID*HID, bl + (size_t)i*HID, xl,
                                nN, HID, HID, 0.f, 0);
        sgemm_k<<<ggrid, 256>>>(hin, Wr + (size_t)i*HID*HID, br + (size_t)i*HID, xr,
                                nN, HID, HID, 0.f, 0);
        gat_k<<<nN, HID>>>(xl, xr, hin, hout, srcp, ea, rp, sorted,
                           gM + (size_t)i*EDGE_IN*HID, gcv + (size_t)i*HID,
                           att + (size_t)i*HID, conv_b + (size_t)i*HID,
                           bn_g + (size_t)i*HID, bn_b + (size_t)i*HID,
                           bn_rm + (size_t)i*HID, bn_rv + (size_t)i*HID, (i >= 1) ? 1 : 0);
        cb ^= 1;
    }

    // output head
    float* hf = cb ? h1 : h0;
    dim3 g2(HALF_HID/128, (nN + 127)/128);
    sgemm_k<<<g2, 256>>>(hf, oW1, ob1, tp, nN, HALF_HID, HID, 0.01f, 1);
    out_k<<<(nN*32 + 255)/256, 256>>>(tp, oW2, ob2, out, nN);
}

// round 3
// speedup vs baseline: 1.1969x; 1.1969x over previous
#include <cuda_runtime.h>
#include <math.h>

#define N_NODES 30000
#define N_EDGES 480000
#define HID 256
#define HID2 512
#define HEADS 8
#define LAYERS 6
#define NODE_IN 13
#define EDGE_IN 10
#define BN_EPS 1e-5f
#define HALF_HID (HID/2)

// ---------------- static scratch (no runtime allocation allowed) ----------------
__device__ __align__(256) float g_h[2][N_NODES*HID];
__device__ __align__(256) float g_xlr[N_NODES*HID2];   // [N][512]: cols 0-255 = xl, 256-511 = xr
__device__ __align__(256) float g_t[N_NODES*HALF_HID];
__device__ __align__(256) float g_Wp[LAYERS][HID*HID2]; // packed [K=256][N=512] (Wl | Wr)
__device__ __align__(256) float g_bp[LAYERS][HID2];
__device__ __align__(256) float g_A[2][EDGE_IN*HID];
__device__ __align__(256) float g_bv[2][HID];
__device__ __align__(256) float g_M[LAYERS][EDGE_IN*HID];
__device__ __align__(256) float g_cvec[LAYERS][HID];
__device__ __align__(256) int   g_row_ptr[N_NODES+1];
__device__ __align__(256) int   g_cursor[N_NODES];
__device__ __align__(256) int   g_sorted[N_EDGES];

// ---------------- CSR build ----------------
__global__ void zero_int_k(int* p, int n){
    for (int i = blockIdx.x*blockDim.x + threadIdx.x; i < n; i += gridDim.x*blockDim.x) p[i] = 0;
}

__global__ void hist_k(const int* __restrict__ dst, int* __restrict__ deg, int n){
    for (int i = blockIdx.x*blockDim.x + threadIdx.x; i < n; i += gridDim.x*blockDim.x)
        atomicAdd(&deg[dst[i]], 1);
}

__global__ void scan_k(int* __restrict__ deg_cursor, int* __restrict__ row_ptr, int n){
    __shared__ int wsum[32];
    __shared__ int s_carry;
    int t = threadIdx.x, lane = t & 31, wid = t >> 5;
    if (t == 0){ s_carry = 0; row_ptr[0] = 0; }
    __syncthreads();
    for (int base = 0; base < n; base += 1024){
        int idx = base + t;
        int v = (idx < n) ? deg_cursor[idx] : 0;
        int x = v;
        #pragma unroll
        for (int o = 1; o < 32; o <<= 1){ int y = __shfl_up_sync(0xffffffffu, x, o); if (lane >= o) x += y; }
        if (lane == 31) wsum[wid] = x;
        __syncthreads();
        if (wid == 0){
            int s = wsum[lane];
            #pragma unroll
            for (int o = 1; o < 32; o <<= 1){ int y = __shfl_up_sync(0xffffffffu, s, o); if (lane >= o) s += y; }
            wsum[lane] = s;
        }
        __syncthreads();
        int c = s_carry;
        int incl = x + (wid ? wsum[wid-1] : 0) + c;
        if (idx < n){ row_ptr[idx+1] = incl; deg_cursor[idx] = incl - v; }
        __syncthreads();
        if (t == 0) s_carry = c + wsum[31];
        __syncthreads();
    }
}

__global__ void scatter_k(const int* __restrict__ dst, int* __restrict__ cursor,
                          int* __restrict__ sorted, int n){
    for (int i = blockIdx.x*blockDim.x + threadIdx.x; i < n; i += gridDim.x*blockDim.x){
        int p = atomicAdd(&cursor[dst[i]], 1);
        sorted[p] = i;
    }
}

// ---------------- initial node embedding ----------------
#define NODES_PER_BLK 16
__global__ void init_h_k(const float* __restrict__ x, const float* __restrict__ W,
                         const float* __restrict__ b, float* __restrict__ h, int n){
    __shared__ float Ws[NODE_IN*HID];
    int t = threadIdx.x;
    #pragma unroll
    for (int j = 0; j < NODE_IN; j++) Ws[j*HID + t] = W[j*HID + t];
    __syncthreads();
    float bb = b[t];
    int n0 = blockIdx.x * NODES_PER_BLK;
    for (int nn = 0; nn < NODES_PER_BLK; nn++){
        int node = n0 + nn;
        if (node >= n) break;
        float s = bb;
        #pragma unroll
        for (int k = 0; k < NODE_IN; k++) s += __ldg(&x[node*NODE_IN + k]) * Ws[k*HID + t];
        h[node*HID + t] = s;
    }
}

// ---------------- weight packing: Wp[l][k][j] = (j<256 ? Wl : Wr) ----------------
__global__ void pack_k(const float* __restrict__ Wl, const float* __restrict__ Wr,
                       const float* __restrict__ bl, const float* __restrict__ br,
                       float* __restrict__ Wp, float* __restrict__ bp){
    int l = blockIdx.y;
    int idx = blockIdx.x*blockDim.x + threadIdx.x;
    if (idx < HID*HID2){
        int k = idx >> 9, j = idx & 511;
        float v = (j < HID) ? Wl[((size_t)l*HID + k)*HID + j]
                            : Wr[((size_t)l*HID + k)*HID + (j - HID)];
        Wp[(size_t)l*HID*HID2 + (size_t)k*HID2 + j] = v;
    }
    if (idx < HID2){
        float b = (idx < HID) ? bl[l*HID + idx] : br[l*HID + idx - HID];
        bp[l*HID2 + idx] = b;
    }
}

// ---------------- edge-feature affine chain ----------------
__global__ void initA_k(const float* __restrict__ edge_W, const float* __restrict__ edge_b,
                        float* __restrict__ A, float* __restrict__ bv){
    int i = blockIdx.x*blockDim.x + threadIdx.x;
    if (i < EDGE_IN*HID) A[i] = edge_W[i];
    if (i < HID) bv[i] = edge_b[i];
}

__global__ void chainM_k(const float* __restrict__ A, const float* __restrict__ bvec,
                         const float* __restrict__ We_i, float* __restrict__ Mo, float* __restrict__ cvo){
    int c = threadIdx.x; int k = blockIdx.x;
    float s = 0.f;
    if (k < EDGE_IN){
        for (int j = 0; j < HID; j++) s += A[k*HID + j] * We_i[j*HID + c];
        Mo[k*HID + c] = s;
    } else {
        for (int j = 0; j < HID; j++) s += bvec[j] * We_i[j*HID + c];
        cvo[c] = s;
    }
}

__global__ void chainU_k(const float* __restrict__ A, const float* __restrict__ bvec,
                         const float* __restrict__ Weu_i, const float* __restrict__ beu_i,
                         float* __restrict__ Ao, float* __restrict__ bo){
    int c = threadIdx.x; int k = blockIdx.x;
    float s = 0.f;
    if (k < EDGE_IN){
        for (int j = 0; j < HID; j++) s += A[k*HID + j] * Weu_i[j*HID + c];
        Ao[k*HID + c] = s;
    } else {
        for (int j = 0; j < HID; j++) s += bvec[j] * Weu_i[j*HID + c];
        bo[c] = s + beu_i[c];
    }
}

// ---------------- tf32 tensor-core GEMM ----------------
// C[M,N] = A[M,K] @ B[K,N] + bias, optional leaky. K % 16 == 0, N % 128 == 0.
// Block tile 128x128xBK16, 256 threads = 8 warps (2x4), warp tile 64x32.
// mma.sync.aligned.m16n8k8 tf32, fp32 accumulate.
#define BM 128
#define BN 128
#define BKT 16
#define PAD 4

__device__ __forceinline__ unsigned f2tf32(float f){
    unsigned u; asm("cvt.rna.tf32.f32 %0, %1;" : "=r"(u) : "f"(f)); return u;
}

__global__ __launch_bounds__(256, 2)
void tf32gemm_k(const float* __restrict__ A, const float* __restrict__ B,
                const float* __restrict__ bias, float* __restrict__ C,
                int M, int N, int K, int ldc, float slope, int leaky)
{
    __shared__ unsigned As[2][BKT][BM+PAD];
    __shared__ unsigned Bs[2][BKT][BN+PAD];

    const int tid  = threadIdx.x;
    const int wid  = tid >> 5, lane = tid & 31;
    const int g    = lane >> 2, tig = lane & 3;
    const int wm   = (wid >> 2) * 64;
    const int wn   = (wid & 3) * 32;
    const int row0 = blockIdx.y * BM, col0 = blockIdx.x * BN;

    // global load assignments
    const int ar = tid & 127;          // A row in tile
    const int aq = (tid >> 7) * 8;     // A k offset: this thread loads k aq..aq+7
    const int bk = wid;                // B k rows: bk and bk+8
    const int bn = lane * 4;           // B col quad
    const int grow = row0 + ar;
    const bool avalid = (grow < M);
    const float* Ap = A + (size_t)grow * K + aq;
    const float* Bp = B + (size_t)bk * N + col0 + bn;

    float acc[4][4][4];
    #pragma unroll
    for (int i = 0; i < 4; i++)
        #pragma unroll
        for (int j = 0; j < 4; j++)
            #pragma unroll
            for (int r = 0; r < 4; r++) acc[i][j][r] = 0.f;

    // prologue: tile 0 -> buf 0
    {
        float4 av0 = make_float4(0,0,0,0), av1 = make_float4(0,0,0,0);
        if (avalid){ av0 = *(const float4*)(Ap); av1 = *(const float4*)(Ap + 4); }
        float4 bv0 = *(const float4*)(Bp);
        float4 bv1 = *(const float4*)(Bp + (size_t)8*N);
        As[0][aq+0][ar] = f2tf32(av0.x); As[0][aq+1][ar] = f2tf32(av0.y);
        As[0][aq+2][ar] = f2tf32(av0.z); As[0][aq+3][ar] = f2tf32(av0.w);
        As[0][aq+4][ar] = f2tf32(av1.x); As[0][aq+5][ar] = f2tf32(av1.y);
        As[0][aq+6][ar] = f2tf32(av1.z); As[0][aq+7][ar] = f2tf32(av1.w);
        Bs[0][bk  ][bn+0] = f2tf32(bv0.x); Bs[0][bk  ][bn+1] = f2tf32(bv0.y);
        Bs[0][bk  ][bn+2] = f2tf32(bv0.z); Bs[0][bk  ][bn+3] = f2tf32(bv0.w);
        Bs[0][bk+8][bn+0] = f2tf32(bv1.x); Bs[0][bk+8][bn+1] = f2tf32(bv1.y);
        Bs[0][bk+8][bn+2] = f2tf32(bv1.z); Bs[0][bk+8][bn+3] = f2tf32(bv1.w);
    }
    __syncthreads();

    const int nk = K / BKT;
    for (int kt = 0; kt < nk; kt++){
        const int buf = kt & 1;
        const bool has_next = (kt + 1 < nk);
        float4 av0, av1, bv0, bv1;
        if (has_next){
            int k0 = (kt + 1) * BKT;
            av0 = make_float4(0,0,0,0); av1 = make_float4(0,0,0,0);
            if (avalid){ av0 = *(const float4*)(Ap + k0); av1 = *(const float4*)(Ap + k0 + 4); }
            bv0 = *(const float4*)(Bp + (size_t)k0*N);
            bv1 = *(const float4*)(Bp + (size_t)(k0+8)*N);
        }

        #pragma unroll
        for (int ks = 0; ks < 2; ks++){
            const int k0 = ks * 8;
            unsigned a[4][4], b[4][2];
            #pragma unroll
            for (int i = 0; i < 4; i++){
                int m = wm + i*16 + g;
                a[i][0] = As[buf][k0+tig  ][m];
                a[i][1] = As[buf][k0+tig  ][m+8];
                a[i][2] = As[buf][k0+tig+4][m];
                a[i][3] = As[buf][k0+tig+4][m+8];
            }
            #pragma unroll
            for (int j = 0; j < 4; j++){
                int n = wn + j*8 + g;
                b[j][0] = Bs[buf][k0+tig  ][n];
                b[j][1] = Bs[buf][k0+tig+4][n];
            }
            #pragma unroll
            for (int i = 0; i < 4; i++)
                #pragma unroll
                for (int j = 0; j < 4; j++){
                    asm volatile(
                        "mma.sync.aligned.m16n8k8.row.col.f32.tf32.tf32.f32 "
                        "{%0,%1,%2,%3}, {%4,%5,%6,%7}, {%8,%9}, {%0,%1,%2,%3};"
                        : "+f"(acc[i][j][0]), "+f"(acc[i][j][1]),
                          "+f"(acc[i][j][2]), "+f"(acc[i][j][3])
                        : "r"(a[i][0]), "r"(a[i][1]), "r"(a[i][2]), "r"(a[i][3]),
                          "r"(b[j][0]), "r"(b[j][1]));
                }
        }

        if (has_next){
            const int nb = buf ^ 1;
            As[nb][aq+0][ar] = f2tf32(av0.x); As[nb][aq+1][ar] = f2tf32(av0.y);
            As[nb][aq+2][ar] = f2tf32(av0.z); As[nb][aq+3][ar] = f2tf32(av0.w);
            As[nb][aq+4][ar] = f2tf32(av1.x); As[nb][aq+5][ar] = f2tf32(av1.y);
            As[nb][aq+6][ar] = f2tf32(av1.z); As[nb][aq+7][ar] = f2tf32(av1.w);
            Bs[nb][bk  ][bn+0] = f2tf32(bv0.x); Bs[nb][bk  ][bn+1] = f2tf32(bv0.y);
            Bs[nb][bk  ][bn+2] = f2tf32(bv0.z); Bs[nb][bk  ][bn+3] = f2tf32(bv0.w);
            Bs[nb][bk+8][bn+0] = f2tf32(bv1.x); Bs[nb][bk+8][bn+1] = f2tf32(bv1.y);
            Bs[nb][bk+8][bn+2] = f2tf32(bv1.z); Bs[nb][bk+8][bn+3] = f2tf32(bv1.w);
        }
        __syncthreads();
    }

    // epilogue
    #pragma unroll
    for (int i = 0; i < 4; i++){
        int r0 = row0 + wm + i*16 + g;
        #pragma unroll
        for (int j = 0; j < 4; j++){
            int c = col0 + wn + j*8 + 2*tig;
            float b0 = bias[c], b1 = bias[c+1];
            if (r0 < M){
                float v0 = acc[i][j][0] + b0;
                float v1 = acc[i][j][1] + b1;
                if (leaky){ v0 = v0 >= 0.f ? v0 : slope*v0; v1 = v1 >= 0.f ? v1 : slope*v1; }
                *(float2*)(C + (size_t)r0*ldc + c) = make_float2(v0, v1);
            }
            if (r0 + 8 < M){
                float v0 = acc[i][j][2] + b0;
                float v1 = acc[i][j][3] + b1;
                if (leaky){ v0 = v0 >= 0.f ? v0 : slope*v0; v1 = v1 >= 0.f ? v1 : slope*v1; }
                *(float2*)(C + (size_t)(r0+8)*ldc + c) = make_float2(v0, v1);
            }
        }
    }
}

// ---------------- fused GATv2 edge phase + BN + leaky + residual ----------------
// xlr layout: row stride 512, xl at +0, xr at +256
__global__ __launch_bounds__(256)
void gat_k(const float* __restrict__ xlr,
           const float* __restrict__ h_in, float* __restrict__ h_out,
           const int* __restrict__ src, const float* __restrict__ ea,
           const int* __restrict__ row_ptr, const int* __restrict__ sorted,
           const float* __restrict__ Mmat, const float* __restrict__ cvec,
           const float* __restrict__ att, const float* __restrict__ conv_b,
           const float* __restrict__ bn_g, const float* __restrict__ bn_b,
           const float* __restrict__ bn_rm, const float* __restrict__ bn_rv,
           int add_res)
{
    __shared__ float Msh[EDGE_IN*HID];
    int t = threadIdx.x;          // channel 0..255; warp = head
    #pragma unroll
    for (int j = 0; j < EDGE_IN; j++) Msh[j*HID + t] = Mmat[j*HID + t];
    int dst = blockIdx.x;
    float xrv  = xlr[(size_t)dst*HID2 + HID + t];
    float attv = att[t];
    float base = xrv + cvec[t];
    int rs = row_ptr[dst], re = row_ptr[dst+1];
    float mmax = -INFINITY, den = 0.f, acc = 0.f;
    __syncthreads();
    for (int p = rs; p < re; p++){
        int e = sorted[p];
        int s = src[e];
        float xlv = __ldg(&xlr[(size_t)s*HID2 + t]);
        const float* eav = ea + (size_t)e*EDGE_IN;
        float v = base + xlv;
        #pragma unroll
        for (int j = 0; j < EDGE_IN; j++) v += __ldg(&eav[j]) * Msh[j*HID + t];
        v = v >= 0.f ? v : 0.2f*v;
        float lg = v * attv;
        #pragma unroll
        for (int o = 16; o > 0; o >>= 1) lg += __shfl_xor_sync(0xffffffffu, lg, o);
        if (lg <= mmax){
            float ee = expf(lg - mmax);
            den += ee; acc += ee * xlv;
        } else {
            float sc = expf(mmax - lg);   // 0 on first edge (mmax = -inf)
            den = den*sc + 1.f;
            acc = acc*sc + xlv;
            mmax = lg;
        }
    }
    float hn = acc / (den + 1e-16f) + conv_b[t];
    hn = (hn - bn_rm[t]) * rsqrtf(bn_rv[t] + BN_EPS) * bn_g[t] + bn_b[t];
    hn = hn >= 0.f ? hn : 0.01f*hn;
    if (add_res) hn += h_in[(size_t)dst*HID + t];
    h_out[(size_t)dst*HID + t] = hn;
}

// ---------------- output head final dot ----------------
__global__ void out_k(const float* __restrict__ tbuf, const float* __restrict__ W2,
                      const float* __restrict__ b2, float* __restrict__ out, int n){
    int gi = blockIdx.x*blockDim.x + threadIdx.x;
    int node = gi >> 5, lane = gi & 31;
    if (node >= n) return;
    float s = 0.f;
    #pragma unroll
    for (int j = lane; j < HALF_HID; j += 32) s += tbuf[node*HALF_HID + j] * __ldg(&W2[j]);
    #pragma unroll
    for (int o = 16; o > 0; o >>= 1) s += __shfl_xor_sync(0xffffffffu, s, o);
    if (lane == 0) out[node] = s + b2[0];
}

// ---------------- host ----------------
extern "C" void kernel_launch(void* const* d_in, const int* in_sizes, int n_in,
                              void* d_out, int out_size)
{
    const float* x      = (const float*)d_in[0];
    const int*   eidx   = (const int*)  d_in[1];
    const float* ea     = (const float*)d_in[2];
    const float* node_W = (const float*)d_in[3];
    const float* node_b = (const float*)d_in[4];
    const float* edge_W = (const float*)d_in[5];
    const float* edge_b = (const float*)d_in[6];
    const float* Wl     = (const float*)d_in[7];
    const float* bl     = (const float*)d_in[8];
    const float* Wr     = (const float*)d_in[9];
    const float* br     = (const float*)d_in[10];
    const float* We     = (const float*)d_in[11];
    const float* att    = (const float*)d_in[12];
    const float* conv_b = (const float*)d_in[13];
    const float* Weu    = (const float*)d_in[14];
    const float* beu    = (const float*)d_in[15];
    const float* bn_g   = (const float*)d_in[16];
    const float* bn_b   = (const float*)d_in[17];
    const float* bn_rm  = (const float*)d_in[18];
    const float* bn_rv  = (const float*)d_in[19];
    const float* oW1    = (const float*)d_in[20];
    const float* ob1    = (const float*)d_in[21];
    const float* oW2    = (const float*)d_in[22];
    const float* ob2    = (const float*)d_in[23];
    float* out = (float*)d_out;

    const int nN = in_sizes[0] / NODE_IN;   // 30000
    const int nE = in_sizes[1] / 2;         // 480000
    const int* srcp = eidx;
    const int* dstp = eidx + nE;

    void* p;
    cudaGetSymbolAddress(&p, g_h);      float* h0 = (float*)p; float* h1 = h0 + (size_t)N_NODES*HID;
    cudaGetSymbolAddress(&p, g_xlr);    float* xlr = (float*)p;
    cudaGetSymbolAddress(&p, g_t);      float* tp = (float*)p;
    cudaGetSymbolAddress(&p, g_Wp);     float* Wp = (float*)p;
    cudaGetSymbolAddress(&p, g_bp);     float* bp = (float*)p;
    cudaGetSymbolAddress(&p, g_A);      float* A0 = (float*)p; float* A1 = A0 + EDGE_IN*HID;
    cudaGetSymbolAddress(&p, g_bv);     float* b0 = (float*)p; float* b1 = b0 + HID;
    cudaGetSymbolAddress(&p, g_M);      float* gM = (float*)p;
    cudaGetSymbolAddress(&p, g_cvec);   float* gcv = (float*)p;
    cudaGetSymbolAddress(&p, g_row_ptr);int* rp = (int*)p;
    cudaGetSymbolAddress(&p, g_cursor); int* cur = (int*)p;
    cudaGetSymbolAddress(&p, g_sorted); int* sorted = (int*)p;

    // CSR build (counting sort by destination)
    zero_int_k<<<128, 256>>>(cur, nN);
    hist_k<<<(nE + 255)/256, 256>>>(dstp, cur, nE);
    scan_k<<<1, 1024>>>(cur, rp, nN);
    scatter_k<<<(nE + 255)/256, 256>>>(dstp, cur, sorted, nE);

    // initial node embedding
    init_h_k<<<(nN + NODES_PER_BLK - 1)/NODES_PER_BLK, HID>>>(x, node_W, node_b, h0, nN);

    // pack Wl|Wr
    {
        dim3 pg((HID*HID2 + 255)/256, LAYERS);
        pack_k<<<pg, 256>>>(Wl, Wr, bl, br, Wp, bp);
    }

    // edge-feature affine chain -> per-layer M (10x256) and cvec (256)
    initA_k<<<(EDGE_IN*HID + 255)/256, 256>>>(edge_W, edge_b, A0, b0);
    {
        float* Ai = A0; float* bi = b0; float* Ao = A1; float* bo = b1;
        for (int i = 0; i < LAYERS; i++){
            chainM_k<<<EDGE_IN + 1, HID>>>(Ai, bi, We + (size_t)i*HID*HID,
                                           gM + (size_t)i*EDGE_IN*HID, gcv + (size_t)i*HID);
            if (i < LAYERS - 1){
                chainU_k<<<EDGE_IN + 1, HID>>>(Ai, bi, Weu + (size_t)i*HID*HID, beu + (size_t)i*HID, Ao, bo);
                float* tA = Ai; Ai = Ao; Ao = tA;
                float* tb = bi; bi = bo; bo = tb;
            }
        }
    }

    // layer loop
    dim3 ggrid(HID2/BN, (nN + BM - 1)/BM);
    int cb = 0;
    for (int i = 0; i < LAYERS; i++){
        float* hin  = cb ? h1 : h0;
        float* hout = cb ? h0 : h1;
        tf32gemm_k<<<ggrid, 256>>>(hin, Wp + (size_t)i*HID*HID2, bp + (size_t)i*HID2, xlr,
                                   nN, HID2, HID, HID2, 0.f, 0);
        gat_k<<<nN, HID>>>(xlr, hin, hout, srcp, ea, rp, sorted,
                           gM + (size_t)i*EDGE_IN*HID, gcv + (size_t)i*HID,
                           att + (size_t)i*HID, conv_b + (size_t)i*HID,
                           bn_g + (size_t)i*HID, bn_b + (size_t)i*HID,
                           bn_rm + (size_t)i*HID, bn_rv + (size_t)i*HID, (i >= 1) ? 1 : 0);
        cb ^= 1;
    }

    // output head
    float* hf = cb ? h1 : h0;
    dim3 g2(HALF_HID/BN, (nN + BM - 1)/BM);
    tf32gemm_k<<<g2, 256>>>(hf, oW1, ob1, tp, nN, HALF_HID, HID, HALF_HID, 0.01f, 1);
    out_k<<<(nN*32 + 255)/256, 256>>>(tp, oW2, ob2, out, nN);
}